// round 1
// baseline (speedup 1.0000x reference)
#include <cuda_runtime.h>
#include <cuda_bf16.h>
#include <cstdint>

#define N_NODES 100000
#define N_EDGES 1600000
#define IN_F    4
#define HDIM    128
#define R_ROB   20
#define OUT_F   2

// ---------------- scratch (device globals; no allocation allowed) ----------
__device__ float g_h  [(size_t)N_NODES * HDIM];   // feature buffer (h1, then h2-gemm out)
__device__ float g_agg[(size_t)N_NODES * HDIM];   // aggregation accumulator
__device__ float g_deg [N_NODES];
__device__ float g_dinv[N_NODES];
__device__ float g_sums[HDIM];
__device__ int   g_insize;

// ---------------- K0: init ----------------
__global__ void k_init() {
    int i = blockIdx.x * blockDim.x + threadIdx.x;
    if (i < N_NODES) g_deg[i] = 1.0f;       // self-loop
    if (i < HDIM)    g_sums[i] = 0.0f;
    if (i == 0)      g_insize = 0;
}

// ---------------- K1: degree ----------------
__global__ void k_deg(const int* __restrict__ dst) {
    int e = blockIdx.x * blockDim.x + threadIdx.x;
    if (e < N_EDGES) atomicAdd(&g_deg[dst[e]], 1.0f);
}

// ---------------- K2: h1 = x@W1 ; dinv ; agg init (self-loop) ; insize -----
// 16 nodes per block, 128 threads (thread j = output column j).
__global__ void k_layer1(const float* __restrict__ x, const float* __restrict__ W1) {
    __shared__ float w[IN_F * HDIM];   // 512 floats
    __shared__ float xs[16 * IN_F];
    int j = threadIdx.x;
    #pragma unroll
    for (int k = j; k < IN_F * HDIM; k += HDIM) w[k] = W1[k];
    int base = blockIdx.x * 16;
    for (int k = j; k < 16 * IN_F; k += HDIM) xs[k] = x[(size_t)base * IN_F + k];
    __syncthreads();

    #pragma unroll
    for (int t = 0; t < 16; t++) {
        int i = base + t;                        // N divisible by 16: no tail
        float h = xs[t*4+0] * w[0*HDIM + j]
                + xs[t*4+1] * w[1*HDIM + j]
                + xs[t*4+2] * w[2*HDIM + j]
                + xs[t*4+3] * w[3*HDIM + j];
        float dv = rsqrtf(g_deg[i]);             // deg >= 1 always
        g_h  [(size_t)i*HDIM + j] = h;
        g_agg[(size_t)i*HDIM + j] = h * dv * dv; // self-loop term
        if (j == 0) {
            g_dinv[i] = dv;
            if (xs[t*4+0] != 0.0f && xs[t*4+1] != 0.0f) atomicAdd(&g_insize, 1);
        }
    }
}

// ---------------- K3/K5: edge aggregation (one warp per edge) --------------
__global__ void k_edge_agg(const int* __restrict__ src, const int* __restrict__ dst) {
    int warp = (blockIdx.x * blockDim.x + threadIdx.x) >> 5;
    int lane = threadIdx.x & 31;
    if (warp >= N_EDGES) return;
    int s = src[warp];                 // uniform within warp -> L1 broadcast
    int d = dst[warp];
    float nrm = g_dinv[s] * g_dinv[d];
    const float4 v = *reinterpret_cast<const float4*>(&g_h[(size_t)s * HDIM + lane * 4]);
    float4 m = make_float4(v.x * nrm, v.y * nrm, v.z * nrm, v.w * nrm);
    float* p = &g_agg[(size_t)d * HDIM + lane * 4];
    asm volatile("red.global.add.v4.f32 [%0], {%1,%2,%3,%4};"
                 :: "l"(p), "f"(m.x), "f"(m.y), "f"(m.z), "f"(m.w)
                 : "memory");
}

// ---------------- K4: t = tanh(agg+b1); h2 = t@W2; agg = h2*dinv^2 ---------
// 32 nodes per block, 128 threads (thread j = output column j).
__global__ void k_layer2(const float* __restrict__ b1, const float* __restrict__ W2) {
    __shared__ float ts[32][HDIM];     // 16 KB
    int j = threadIdx.x;
    int base = blockIdx.x * 32;        // N divisible by 32: no tail
    float bj = b1[j];
    #pragma unroll 4
    for (int t = 0; t < 32; t++) {
        int i = base + t;
        ts[t][j] = tanhf(g_agg[(size_t)i*HDIM + j] + bj);
    }
    __syncthreads();

    float acc[32];
    #pragma unroll
    for (int t = 0; t < 32; t++) acc[t] = 0.0f;

    #pragma unroll 4
    for (int k = 0; k < HDIM; k++) {
        float wv = W2[k * HDIM + j];   // coalesced across threads
        #pragma unroll
        for (int t = 0; t < 32; t++) acc[t] += ts[t][k] * wv;  // smem broadcast
    }

    #pragma unroll 4
    for (int t = 0; t < 32; t++) {
        int i = base + t;
        float dv = g_dinv[i];
        g_h  [(size_t)i*HDIM + j] = acc[t];
        g_agg[(size_t)i*HDIM + j] = acc[t] * dv * dv;   // self-loop for layer 2
    }
}

// ---------------- K6: h = tanh(agg+b2); column-sum pooling ----------------
__global__ void k_pool(const float* __restrict__ b2) {
    int j = threadIdx.x;               // 128 threads
    float bj = b2[j];
    float part = 0.0f;
    for (int i = blockIdx.x; i < N_NODES; i += gridDim.x)
        part += tanhf(g_agg[(size_t)i*HDIM + j] + bj);
    atomicAdd(&g_sums[j], part);
}

// ---------------- K7: pooled mean, FC, mask, write 40 outputs -------------
__global__ void k_out(const float* __restrict__ Wfc, const float* __restrict__ bfc,
                      float* __restrict__ out) {
    __shared__ float pooled[HDIM];
    int t = threadIdx.x;               // 128 threads
    pooled[t] = g_sums[t] * (1.0f / (float)N_NODES);
    __syncthreads();
    if (t < R_ROB * OUT_F) {
        float acc = bfc[t];
        #pragma unroll 8
        for (int k = 0; k < HDIM; k++)
            acc += pooled[k] * Wfc[k * (R_ROB * OUT_F) + t];
        int r = t / OUT_F;
        out[t] = (r < g_insize) ? acc : 0.0f;
    }
}

// ---------------- launch ----------------
extern "C" void kernel_launch(void* const* d_in, const int* in_sizes, int n_in,
                              void* d_out, int out_size) {
    const float* x   = (const float*)d_in[0];
    const int*   ei  = (const int*)  d_in[1];
    // d_in[2] = batch (all zeros) -- unused
    const float* W1  = (const float*)d_in[3];
    const float* b1  = (const float*)d_in[4];
    const float* W2  = (const float*)d_in[5];
    const float* b2  = (const float*)d_in[6];
    const float* Wfc = (const float*)d_in[7];
    const float* bfc = (const float*)d_in[8];
    float* out = (float*)d_out;

    const int* src = ei;
    const int* dst = ei + N_EDGES;

    k_init<<<(N_NODES + 255) / 256, 256>>>();
    k_deg <<<(N_EDGES + 255) / 256, 256>>>(dst);
    k_layer1<<<N_NODES / 16, 128>>>(x, W1);

    int agg_blocks = (N_EDGES + 7) / 8;            // 8 warps/block, 1 edge/warp
    k_edge_agg<<<agg_blocks, 256>>>(src, dst);

    k_layer2<<<N_NODES / 32, 128>>>(b1, W2);

    k_edge_agg<<<agg_blocks, 256>>>(src, dst);

    k_pool<<<592, 128>>>(b2);
    k_out <<<1, 128>>>(Wfc, bfc, out);
}

// round 3
// speedup vs baseline: 1.6380x; 1.6380x over previous
#include <cuda_runtime.h>
#include <cuda_bf16.h>
#include <cstdint>

#define N_NODES 100000
#define N_EDGES 1600000
#define IN_F    4
#define HDIM    128
#define R_ROB   20
#define OUT_F   2

#define SCAN_B      1024
#define NSCAN_BLKS  ((N_NODES + SCAN_B - 1) / SCAN_B)   // 98

// ---------------- scratch (device globals; no allocation allowed) ----------
__device__ float g_h  [(size_t)N_NODES * HDIM];   // feature buffer
__device__ float g_agg[(size_t)N_NODES * HDIM];   // aggregation result
__device__ float g_dinv[N_NODES];
__device__ float g_sums[HDIM];
__device__ int   g_insize;

__device__ int g_cnt   [N_NODES];     // in-degree (real edges only)
__device__ int g_excl  [N_NODES];     // per-block exclusive scan
__device__ int g_rowptr[N_NODES];     // CSR row start
__device__ int g_cursor[N_NODES];     // fill cursors
__device__ int g_bsum  [NSCAN_BLKS];
__device__ int g_boff  [NSCAN_BLKS];
__device__ int g_esrc  [N_EDGES];     // CSR: src node per slot

// ---------------- K0: init ----------------
__global__ void k_init() {
    int i = blockIdx.x * blockDim.x + threadIdx.x;
    if (i < N_NODES) g_cnt[i] = 0;
    if (i < HDIM)    g_sums[i] = 0.0f;
    if (i == 0)      g_insize = 0;
}

// ---------------- K1: count in-degree ----------------
__global__ void k_count(const int* __restrict__ dst) {
    int e = blockIdx.x * blockDim.x + threadIdx.x;
    if (e < N_EDGES) atomicAdd(&g_cnt[dst[e]], 1);
}

// ---------------- K2a: per-block inclusive scan ----------------
__global__ void k_scan1() {
    __shared__ int sm[SCAN_B];
    int i = blockIdx.x * SCAN_B + threadIdx.x;
    int v = (i < N_NODES) ? g_cnt[i] : 0;
    sm[threadIdx.x] = v;
    __syncthreads();
    #pragma unroll
    for (int off = 1; off < SCAN_B; off <<= 1) {
        int t = (threadIdx.x >= off) ? sm[threadIdx.x - off] : 0;
        __syncthreads();
        sm[threadIdx.x] += t;
        __syncthreads();
    }
    if (i < N_NODES) g_excl[i] = sm[threadIdx.x] - v;
    if (threadIdx.x == SCAN_B - 1) g_bsum[blockIdx.x] = sm[SCAN_B - 1];
}

// ---------------- K2b: scan of block sums ----------------
__global__ void k_scan2() {
    if (threadIdx.x == 0) {
        int run = 0;
        #pragma unroll 2
        for (int b = 0; b < NSCAN_BLKS; b++) { g_boff[b] = run; run += g_bsum[b]; }
    }
}

// ---------------- K2c: rowptr, cursors, dinv ----------------
__global__ void k_scan3() {
    int i = blockIdx.x * blockDim.x + threadIdx.x;
    if (i >= N_NODES) return;
    int base = g_excl[i] + g_boff[i >> 10];
    g_rowptr[i] = base;
    g_cursor[i] = base;
    g_dinv[i]   = rsqrtf((float)g_cnt[i] + 1.0f);   // +1 self-loop
}

// ---------------- K3: fill CSR ----------------
__global__ void k_fill(const int* __restrict__ src, const int* __restrict__ dst) {
    int e = blockIdx.x * blockDim.x + threadIdx.x;
    if (e >= N_EDGES) return;
    int pos = atomicAdd(&g_cursor[dst[e]], 1);
    g_esrc[pos] = src[e];
}

// ---------------- K4: h1 = x@W1 ; insize -----------------------------------
__global__ void k_layer1(const float* __restrict__ x, const float* __restrict__ W1) {
    __shared__ float w[IN_F * HDIM];
    __shared__ float xs[16 * IN_F];
    int j = threadIdx.x;
    #pragma unroll
    for (int k = j; k < IN_F * HDIM; k += HDIM) w[k] = W1[k];
    int base = blockIdx.x * 16;
    for (int k = j; k < 16 * IN_F; k += HDIM) xs[k] = x[(size_t)base * IN_F + k];
    __syncthreads();

    #pragma unroll
    for (int t = 0; t < 16; t++) {
        int i = base + t;
        float h = xs[t*4+0] * w[0*HDIM + j]
                + xs[t*4+1] * w[1*HDIM + j]
                + xs[t*4+2] * w[2*HDIM + j]
                + xs[t*4+3] * w[3*HDIM + j];
        g_h[(size_t)i*HDIM + j] = h;
        if (j == 0 && xs[t*4+0] != 0.0f && xs[t*4+1] != 0.0f) atomicAdd(&g_insize, 1);
    }
}

// ---------------- K5/K7: gather aggregation (warp per dst node) ------------
// DIR=0: read g_h  -> write g_agg.   DIR=1: same (both layers read g_h).
// Globals referenced from DEVICE code only (host cannot pass their address).
template<int DIR>
__global__ void k_gather() {
    int node = (blockIdx.x * blockDim.x + threadIdx.x) >> 5;
    int lane = threadIdx.x & 31;
    if (node >= N_NODES) return;
    int   start = g_rowptr[node];
    int   cnt   = g_cnt[node];
    float dvd   = g_dinv[node];

    const float4* hv   = (const float4*)g_h;
    float4*       outv = (float4*)g_agg;

    float4 a = hv[(size_t)node * 32 + lane];
    float s2 = dvd * dvd;
    float4 acc = make_float4(a.x * s2, a.y * s2, a.z * s2, a.w * s2);

    for (int k = 0; k < cnt; k++) {
        int   s  = __ldg(&g_esrc[start + k]);      // uniform in warp -> broadcast
        float nr = g_dinv[s] * dvd;
        float4 v = hv[(size_t)s * 32 + lane];
        acc.x += v.x * nr; acc.y += v.y * nr;
        acc.z += v.z * nr; acc.w += v.w * nr;
    }
    outv[(size_t)node * 32 + lane] = acc;
}

// ---------------- K6: t = tanh(agg+b1); h2 = t@W2 --------------------------
// 64 nodes x 128 cols per block, 256 threads, 4x8 register tile per thread.
__global__ void k_layer2(const float* __restrict__ b1, const float* __restrict__ W2) {
    __shared__ float ts[64][HDIM];     // 32 KB
    int tid  = threadIdx.x;
    int base = blockIdx.x * 64;

    for (int idx = tid; idx < 64 * HDIM; idx += 256) {
        int t = idx >> 7, c = idx & 127;
        int node = base + t;
        ts[t][c] = (node < N_NODES) ? tanhf(g_agg[(size_t)node*HDIM + c] + b1[c]) : 0.0f;
    }
    __syncthreads();

    int a = tid >> 4;          // 0..15 : node group (4 nodes)
    int b = tid & 15;          // 0..15 : col group  (8 cols)

    float acc[4][8];
    #pragma unroll
    for (int i = 0; i < 4; i++)
        #pragma unroll
        for (int j = 0; j < 8; j++) acc[i][j] = 0.0f;

    #pragma unroll 4
    for (int k = 0; k < HDIM; k++) {
        float a0 = ts[a*4+0][k], a1 = ts[a*4+1][k];
        float a2 = ts[a*4+2][k], a3 = ts[a*4+3][k];
        float4 w0 = *(const float4*)&W2[k*HDIM + b*8];      // L1-resident (64KB)
        float4 w1 = *(const float4*)&W2[k*HDIM + b*8 + 4];
        float wv[8] = {w0.x,w0.y,w0.z,w0.w,w1.x,w1.y,w1.z,w1.w};
        #pragma unroll
        for (int j = 0; j < 8; j++) {
            acc[0][j] += a0 * wv[j];
            acc[1][j] += a1 * wv[j];
            acc[2][j] += a2 * wv[j];
            acc[3][j] += a3 * wv[j];
        }
    }

    #pragma unroll
    for (int i = 0; i < 4; i++) {
        int node = base + a*4 + i;
        if (node < N_NODES) {
            float* p = &g_h[(size_t)node*HDIM + b*8];
            *(float4*)p       = make_float4(acc[i][0], acc[i][1], acc[i][2], acc[i][3]);
            *(float4*)(p + 4) = make_float4(acc[i][4], acc[i][5], acc[i][6], acc[i][7]);
        }
    }
}

// ---------------- K8: h = tanh(agg+b2); column-sum pooling ----------------
__global__ void k_pool(const float* __restrict__ b2) {
    int j = threadIdx.x;
    float bj = b2[j];
    float part = 0.0f;
    for (int i = blockIdx.x; i < N_NODES; i += gridDim.x)
        part += tanhf(g_agg[(size_t)i*HDIM + j] + bj);
    atomicAdd(&g_sums[j], part);
}

// ---------------- K9: pooled mean, FC, mask -------------------------------
__global__ void k_out(const float* __restrict__ Wfc, const float* __restrict__ bfc,
                      float* __restrict__ out) {
    __shared__ float pooled[HDIM];
    int t = threadIdx.x;
    pooled[t] = g_sums[t] * (1.0f / (float)N_NODES);
    __syncthreads();
    if (t < R_ROB * OUT_F) {
        float acc = bfc[t];
        #pragma unroll 8
        for (int k = 0; k < HDIM; k++)
            acc += pooled[k] * Wfc[k * (R_ROB * OUT_F) + t];
        int r = t / OUT_F;
        out[t] = (r < g_insize) ? acc : 0.0f;
    }
}

// ---------------- launch ----------------
extern "C" void kernel_launch(void* const* d_in, const int* in_sizes, int n_in,
                              void* d_out, int out_size) {
    const float* x   = (const float*)d_in[0];
    const int*   ei  = (const int*)  d_in[1];
    const float* W1  = (const float*)d_in[3];
    const float* b1  = (const float*)d_in[4];
    const float* W2  = (const float*)d_in[5];
    const float* b2  = (const float*)d_in[6];
    const float* Wfc = (const float*)d_in[7];
    const float* bfc = (const float*)d_in[8];
    float* out = (float*)d_out;

    const int* src = ei;
    const int* dst = ei + N_EDGES;

    k_init <<<(N_NODES + 255) / 256, 256>>>();
    k_count<<<(N_EDGES + 255) / 256, 256>>>(dst);
    k_scan1<<<NSCAN_BLKS, SCAN_B>>>();
    k_scan2<<<1, 32>>>();
    k_scan3<<<(N_NODES + 255) / 256, 256>>>();
    k_fill <<<(N_EDGES + 255) / 256, 256>>>(src, dst);

    k_layer1<<<N_NODES / 16, 128>>>(x, W1);

    int gthr_blocks = (N_NODES * 32 + 255) / 256;          // warp per node
    k_gather<0><<<gthr_blocks, 256>>>();

    k_layer2<<<(N_NODES + 63) / 64, 256>>>(b1, W2);

    k_gather<1><<<gthr_blocks, 256>>>();

    k_pool<<<592, 128>>>(b2);
    k_out <<<1, 128>>>(Wfc, bfc, out);
}

// round 4
// speedup vs baseline: 1.8680x; 1.1404x over previous
#include <cuda_runtime.h>
#include <cuda_bf16.h>
#include <cuda_fp16.h>
#include <cstdint>

#define N_NODES 100000
#define N_EDGES 1600000
#define IN_F    4
#define HDIM    128
#define R_ROB   20
#define OUT_F   2

#define SCAN_B      1024
#define NSCAN_BLKS  ((N_NODES + SCAN_B - 1) / SCAN_B)   // 98

// ---------------- scratch (device globals; no allocation allowed) ----------
__device__ __half2 g_hh [(size_t)N_NODES * HDIM / 2];  // fp16 feature buffer (gather input)
__device__ float   g_agg[(size_t)N_NODES * HDIM];      // aggregation result (fp32)
__device__ float   g_dinv[N_NODES];
__device__ float   g_sums[HDIM];
__device__ int     g_insize;

__device__ int g_cnt   [N_NODES];
__device__ int g_excl  [N_NODES];
__device__ int g_rowptr[N_NODES];
__device__ int g_cursor[N_NODES];
__device__ int g_bsum  [NSCAN_BLKS];
__device__ int g_boff  [NSCAN_BLKS];
__device__ int g_esrc  [N_EDGES];

// ---------------- K0: init ----------------
__global__ void k_init() {
    int i = blockIdx.x * blockDim.x + threadIdx.x;
    if (i < N_NODES) g_cnt[i] = 0;
    if (i < HDIM)    g_sums[i] = 0.0f;
    if (i == 0)      g_insize = 0;
}

// ---------------- K1: count in-degree ----------------
__global__ void k_count(const int* __restrict__ dst) {
    int e = blockIdx.x * blockDim.x + threadIdx.x;
    if (e < N_EDGES) atomicAdd(&g_cnt[dst[e]], 1);
}

// ---------------- K2a: per-block inclusive scan ----------------
__global__ void k_scan1() {
    __shared__ int sm[SCAN_B];
    int i = blockIdx.x * SCAN_B + threadIdx.x;
    int v = (i < N_NODES) ? g_cnt[i] : 0;
    sm[threadIdx.x] = v;
    __syncthreads();
    #pragma unroll
    for (int off = 1; off < SCAN_B; off <<= 1) {
        int t = (threadIdx.x >= off) ? sm[threadIdx.x - off] : 0;
        __syncthreads();
        sm[threadIdx.x] += t;
        __syncthreads();
    }
    if (i < N_NODES) g_excl[i] = sm[threadIdx.x] - v;
    if (threadIdx.x == SCAN_B - 1) g_bsum[blockIdx.x] = sm[SCAN_B - 1];
}

// ---------------- K2b: parallel exclusive scan of 98 block sums ------------
__global__ void k_scan2() {
    __shared__ int sm[128];
    int t = threadIdx.x;
    int v = (t < NSCAN_BLKS) ? g_bsum[t] : 0;
    sm[t] = v;
    __syncthreads();
    #pragma unroll
    for (int off = 1; off < 128; off <<= 1) {
        int u = (t >= off) ? sm[t - off] : 0;
        __syncthreads();
        sm[t] += u;
        __syncthreads();
    }
    if (t < NSCAN_BLKS) g_boff[t] = sm[t] - v;   // exclusive
}

// ---------------- K2c: rowptr, cursors, dinv ----------------
__global__ void k_scan3() {
    int i = blockIdx.x * blockDim.x + threadIdx.x;
    if (i >= N_NODES) return;
    int base = g_excl[i] + g_boff[i >> 10];
    g_rowptr[i] = base;
    g_cursor[i] = base;
    g_dinv[i]   = rsqrtf((float)g_cnt[i] + 1.0f);   // +1 self-loop
}

// ---------------- K3: fill CSR ----------------
__global__ void k_fill(const int* __restrict__ src, const int* __restrict__ dst) {
    int e = blockIdx.x * blockDim.x + threadIdx.x;
    if (e >= N_EDGES) return;
    int pos = atomicAdd(&g_cursor[dst[e]], 1);
    g_esrc[pos] = src[e];
}

// ---------------- K4: h1 = x@W1 (fp16 out) ; insize ------------------------
__global__ void k_layer1(const float* __restrict__ x, const float* __restrict__ W1) {
    __shared__ float w[IN_F * HDIM];
    __shared__ float xs[16 * IN_F];
    int j = threadIdx.x;
    #pragma unroll
    for (int k = j; k < IN_F * HDIM; k += HDIM) w[k] = W1[k];
    int base = blockIdx.x * 16;
    for (int k = j; k < 16 * IN_F; k += HDIM) xs[k] = x[(size_t)base * IN_F + k];
    __syncthreads();

    __half* hh = (__half*)g_hh;
    #pragma unroll
    for (int t = 0; t < 16; t++) {
        int i = base + t;
        float h = xs[t*4+0] * w[0*HDIM + j]
                + xs[t*4+1] * w[1*HDIM + j]
                + xs[t*4+2] * w[2*HDIM + j]
                + xs[t*4+3] * w[3*HDIM + j];
        hh[(size_t)i*HDIM + j] = __float2half(h);
        if (j == 0 && xs[t*4+0] != 0.0f && xs[t*4+1] != 0.0f) atomicAdd(&g_insize, 1);
    }
}

// ---------------- K5/K7: gather aggregation (warp per dst node, fp16 in) ---
template<int DIR>
__global__ void k_gather() {
    int node = (blockIdx.x * blockDim.x + threadIdx.x) >> 5;
    int lane = threadIdx.x & 31;
    if (node >= N_NODES) return;
    int   start = g_rowptr[node];
    int   cnt   = g_cnt[node];
    float dvd   = g_dinv[node];

    const uint2* hv = (const uint2*)g_hh;   // 8B = 4 halfs per lane

    uint2 u = hv[(size_t)node * 32 + lane];
    __half2 p0 = *reinterpret_cast<__half2*>(&u.x);
    __half2 p1 = *reinterpret_cast<__half2*>(&u.y);
    float2 f0 = __half22float2(p0);
    float2 f1 = __half22float2(p1);
    float s2 = dvd * dvd;
    float4 acc = make_float4(f0.x * s2, f0.y * s2, f1.x * s2, f1.y * s2);

    for (int k = 0; k < cnt; k++) {
        int   s  = __ldg(&g_esrc[start + k]);      // uniform in warp -> broadcast
        float nr = g_dinv[s] * dvd;
        uint2 v = hv[(size_t)s * 32 + lane];
        __half2 q0 = *reinterpret_cast<__half2*>(&v.x);
        __half2 q1 = *reinterpret_cast<__half2*>(&v.y);
        float2 g0 = __half22float2(q0);
        float2 g1 = __half22float2(q1);
        acc.x += g0.x * nr; acc.y += g0.y * nr;
        acc.z += g1.x * nr; acc.w += g1.y * nr;
    }
    ((float4*)g_agg)[(size_t)node * 32 + lane] = acc;
}

// ---------------- K6: t = tanh(agg+b1); h2 = t@W2 (fp16 out) --------------
__global__ void k_layer2(const float* __restrict__ b1, const float* __restrict__ W2) {
    __shared__ float ts[64][HDIM];     // 32 KB
    int tid  = threadIdx.x;
    int base = blockIdx.x * 64;

    for (int idx = tid; idx < 64 * HDIM; idx += 256) {
        int t = idx >> 7, c = idx & 127;
        int node = base + t;
        ts[t][c] = (node < N_NODES) ? tanhf(g_agg[(size_t)node*HDIM + c] + b1[c]) : 0.0f;
    }
    __syncthreads();

    int a = tid >> 4;          // 0..15 : node group (4 nodes)
    int b = tid & 15;          // 0..15 : col group  (8 cols)

    float acc[4][8];
    #pragma unroll
    for (int i = 0; i < 4; i++)
        #pragma unroll
        for (int j = 0; j < 8; j++) acc[i][j] = 0.0f;

    #pragma unroll 4
    for (int k = 0; k < HDIM; k++) {
        float a0 = ts[a*4+0][k], a1 = ts[a*4+1][k];
        float a2 = ts[a*4+2][k], a3 = ts[a*4+3][k];
        float4 w0 = *(const float4*)&W2[k*HDIM + b*8];
        float4 w1 = *(const float4*)&W2[k*HDIM + b*8 + 4];
        float wv[8] = {w0.x,w0.y,w0.z,w0.w,w1.x,w1.y,w1.z,w1.w};
        #pragma unroll
        for (int j = 0; j < 8; j++) {
            acc[0][j] += a0 * wv[j];
            acc[1][j] += a1 * wv[j];
            acc[2][j] += a2 * wv[j];
            acc[3][j] += a3 * wv[j];
        }
    }

    __half* hh = (__half*)g_hh;
    #pragma unroll
    for (int i = 0; i < 4; i++) {
        int node = base + a*4 + i;
        if (node < N_NODES) {
            __half2 h2v[4];
            #pragma unroll
            for (int j = 0; j < 4; j++)
                h2v[j] = __floats2half2_rn(acc[i][2*j], acc[i][2*j+1]);
            *(uint4*)&hh[(size_t)node*HDIM + b*8] = *(uint4*)h2v;  // 8 halfs = 16B
        }
    }
}

// ---------------- K8: h = tanh(agg+b2); column-sum pooling ----------------
__global__ void k_pool(const float* __restrict__ b2) {
    int j = threadIdx.x;
    float bj = b2[j];
    float part = 0.0f;
    for (int i = blockIdx.x; i < N_NODES; i += gridDim.x)
        part += tanhf(g_agg[(size_t)i*HDIM + j] + bj);
    atomicAdd(&g_sums[j], part);
}

// ---------------- K9: pooled mean, FC, mask -------------------------------
__global__ void k_out(const float* __restrict__ Wfc, const float* __restrict__ bfc,
                      float* __restrict__ out) {
    __shared__ float pooled[HDIM];
    int t = threadIdx.x;
    pooled[t] = g_sums[t] * (1.0f / (float)N_NODES);
    __syncthreads();
    if (t < R_ROB * OUT_F) {
        float acc = bfc[t];
        #pragma unroll 8
        for (int k = 0; k < HDIM; k++)
            acc += pooled[k] * Wfc[k * (R_ROB * OUT_F) + t];
        int r = t / OUT_F;
        out[t] = (r < g_insize) ? acc : 0.0f;
    }
}

// ---------------- launch ----------------
extern "C" void kernel_launch(void* const* d_in, const int* in_sizes, int n_in,
                              void* d_out, int out_size) {
    const float* x   = (const float*)d_in[0];
    const int*   ei  = (const int*)  d_in[1];
    const float* W1  = (const float*)d_in[3];
    const float* b1  = (const float*)d_in[4];
    const float* W2  = (const float*)d_in[5];
    const float* b2  = (const float*)d_in[6];
    const float* Wfc = (const float*)d_in[7];
    const float* bfc = (const float*)d_in[8];
    float* out = (float*)d_out;

    const int* src = ei;
    const int* dst = ei + N_EDGES;

    k_init <<<(N_NODES + 255) / 256, 256>>>();
    k_count<<<(N_EDGES + 255) / 256, 256>>>(dst);
    k_scan1<<<NSCAN_BLKS, SCAN_B>>>();
    k_scan2<<<1, 128>>>();
    k_scan3<<<(N_NODES + 255) / 256, 256>>>();
    k_fill <<<(N_EDGES + 255) / 256, 256>>>(src, dst);

    k_layer1<<<N_NODES / 16, 128>>>(x, W1);

    int gthr_blocks = (N_NODES * 32 + 255) / 256;          // warp per node
    k_gather<0><<<gthr_blocks, 256>>>();

    k_layer2<<<(N_NODES + 63) / 64, 256>>>(b1, W2);

    k_gather<1><<<gthr_blocks, 256>>>();

    k_pool<<<592, 128>>>(b2);
    k_out <<<1, 128>>>(Wfc, bfc, out);
}